// round 7
// baseline (speedup 1.0000x reference)
#include <cuda_runtime.h>
#include <math.h>

#define NPTS 131072   // B*N
#define NB   65536    // N (points per batch)
#define KNN  32
#define FD   64

typedef unsigned long long u64;

// Scratch (no allocations allowed)
__device__ float g_x1[NPTS * 16];    // 8 MB   lrelu(feat @ Wi^T)
__device__ float g_x2[NPTS * 32];    // 16 MB  [g1 | f1]
__device__ float g_x3[NPTS * 64];    // 32 MB  [g2 | f2]
__device__ float g_res[NPTS * 64];   // 32 MB  lrelu(feat @ Wr^T + br)

// Pre-packed k-pair weights for k_final (wf only):
// g_wq0[dhalf][k2][dloc] = {wf[D][2*k2], wf[D][2*k2+1]},  D = dhalf*32+dloc
__device__ __align__(16) u64 g_wq0[2][32][32];

__device__ __forceinline__ float lrelu(float x) { return fmaxf(x, 0.2f * x); }

// ---- packed f32x2 helpers (sm_103a FFMA2 path) ----
__device__ __forceinline__ u64 fma2(u64 a, u64 b, u64 c) {
    u64 r;
    asm("fma.rn.f32x2 %0, %1, %2, %3;" : "=l"(r) : "l"(a), "l"(b), "l"(c));
    return r;
}
__device__ __forceinline__ u64 pk2(float x, float y) {
    u64 r;
    asm("mov.b64 %0, {%1, %2};" : "=l"(r) : "f"(x), "f"(y));
    return r;
}
__device__ __forceinline__ float2 up2(u64 a) {
    float2 v;
    asm("mov.b64 {%0, %1}, %2;" : "=f"(v.x), "=f"(v.y) : "l"(a));
    return v;
}
#define C06_2 0x3F19999A3F19999AULL   // {0.6f, 0.6f}
#define C04_2 0x3ECCCCCD3ECCCCCDULL   // {0.4f, 0.4f}
#define ABSM  0x7FFFFFFF7FFFFFFFULL

// packed lrelu accumulate: acc += lrelu2(s)  where lrelu(x)=0.6x+0.4|x|
__device__ __forceinline__ u64 lrelu_acc2(u64 s, u64 acc) {
    acc = fma2(s, C06_2, acc);
    acc = fma2(s & ABSM, C04_2, acc);
    return acc;
}

// ---------------------------------------------------------------------------
// K1: fused  x1 = lrelu(feat @ wi^T + bi)  (16)   and
//            g_res = lrelu(feat @ wr^T + br)  (64)
// Block: 64 points, 256 threads. One feat tile load feeds both GEMMs.
// Block 0 additionally packs wf k-pairs into g_wq0 for k_final.
// ---------------------------------------------------------------------------
__global__ __launch_bounds__(256) void k_init_res(
    const float* __restrict__ feat,
    const float* __restrict__ wi, const float* __restrict__ bi,
    const float* __restrict__ wr, const float* __restrict__ br,
    const float* __restrict__ wf)
{
    __shared__ float4 sf4[64 * 17];                // 64 pts x 64 k, padded
    __shared__ float  swt[64 * 16];                // wi transposed [k][d]
    __shared__ __align__(16) u64 swr[32][64];      // wr k-pairs [k2][drow]
    __shared__ float sbi[16], sbr[64];

    int tid = threadIdx.x;
    int fb  = blockIdx.x * 64;

    // stage feat tile (64 rows x 256B contiguous)
    const float4* f4 = (const float4*)feat + (size_t)fb * 16;
#pragma unroll
    for (int e = tid; e < 1024; e += 256) {
        int p = e >> 4, k4 = e & 15;
        sf4[p * 17 + k4] = f4[e];
    }
    // stage wi transposed
#pragma unroll
    for (int e = tid; e < 1024; e += 256) {
        int d = e >> 6, k = e & 63;
        swt[k * 16 + d] = wi[e];
    }
    // stage wr k-pairs
#pragma unroll
    for (int e = tid; e < 2048; e += 256) {
        int drow = e >> 5, k2 = e & 31;
        swr[k2][drow] = *(const u64*)(wr + (size_t)drow * 64 + k2 * 2);
    }
    if (tid < 16) sbi[tid] = bi[tid];
    if (tid < 64) sbr[tid] = br[tid];

    // block 0: pack wf for k_final (runs once, overlapped with grid)
    if (blockIdx.x == 0) {
#pragma unroll
        for (int e = tid; e < 2048; e += 256) {
            int dh = e >> 10, k2 = (e >> 5) & 31, dloc = e & 31;
            g_wq0[dh][k2][dloc] =
                *(const u64*)(wf + (size_t)(dh * 32 + dloc) * 64 + k2 * 2);
        }
    }
    __syncthreads();

    // ---------------- residual GEMM: 4 pts x 4 outs per thread ----------------
    int c    = tid & 15;            // out group: d = c*4 .. c*4+3
    int rw   = tid >> 4;            // 0..15; pts = rw + 16*i
    int dloc = c * 4;

    u64 racc[4][4];
#pragma unroll
    for (int i = 0; i < 4; i++)
#pragma unroll
        for (int j = 0; j < 4; j++) racc[i][j] = 0ull;

#pragma unroll
    for (int k4 = 0; k4 < 16; k4++) {
        ulonglong2 wv0 = *(const ulonglong2*)&swr[2 * k4][dloc];
        ulonglong2 wv1 = *(const ulonglong2*)&swr[2 * k4][dloc + 2];
        ulonglong2 wv2 = *(const ulonglong2*)&swr[2 * k4 + 1][dloc];
        ulonglong2 wv3 = *(const ulonglong2*)&swr[2 * k4 + 1][dloc + 2];
#pragma unroll
        for (int i = 0; i < 4; i++) {
            ulonglong2 xv = *(const ulonglong2*)&sf4[(rw + 16 * i) * 17 + k4];
            racc[i][0] = fma2(xv.x, wv0.x, racc[i][0]);
            racc[i][0] = fma2(xv.y, wv2.x, racc[i][0]);
            racc[i][1] = fma2(xv.x, wv0.y, racc[i][1]);
            racc[i][1] = fma2(xv.y, wv2.y, racc[i][1]);
            racc[i][2] = fma2(xv.x, wv1.x, racc[i][2]);
            racc[i][2] = fma2(xv.y, wv3.x, racc[i][2]);
            racc[i][3] = fma2(xv.x, wv1.y, racc[i][3]);
            racc[i][3] = fma2(xv.y, wv3.y, racc[i][3]);
        }
    }

    {
        float4* res4 = (float4*)g_res;
#pragma unroll
        for (int i = 0; i < 4; i++) {
            int p = rw + 16 * i;
            float4 v;
#pragma unroll
            for (int j = 0; j < 4; j++) {
                float2 s = up2(racc[i][j]);
                (&v.x)[j] = lrelu(s.x + s.y + sbr[dloc + j]);
            }
            res4[(size_t)(fb + p) * 16 + c] = v;
        }
    }

    // ---------------- x1 GEMM: 1 dim x 4 pts per thread (scalar) --------------
    {
        int d    = tid & 15;
        int prow = tid >> 4;
        const float* sf = (const float*)sf4;    // row stride 68 floats
#pragma unroll
        for (int it = 0; it < 4; it++) {
            int p = prow + it * 16;
            float acc = sbi[d];
#pragma unroll
            for (int k = 0; k < 64; k++)
                acc = fmaf(sf[p * 68 + k], swt[k * 16 + d], acc);
            g_x1[(size_t)(fb + p) * 16 + d] = lrelu(acc);
        }
    }
}

// ---------------------------------------------------------------------------
// K2: fused geo-MLPs of lfa1 + lfa2 (shared geometry) + x1 gather-mean.
// One warp per point. Geo staged SoA in SMEM; packed f32x2 over neighbor pairs.
// ---------------------------------------------------------------------------
__global__ __launch_bounds__(256) void k_lfa_geo(
    const float* __restrict__ pts, const int* __restrict__ idx,
    const float* __restrict__ w1, const float* __restrict__ b1,
    const float* __restrict__ w2, const float* __restrict__ b2)
{
    __shared__ __align__(16) float sgx[8][32];
    __shared__ __align__(16) float sgy[8][32];
    __shared__ __align__(16) float sgz[8][32];
    __shared__ __align__(16) float sgd[8][32];
    __shared__ int sidx[8][32];

    int lane = threadIdx.x & 31;
    int wid  = threadIdx.x >> 5;
    int r    = blockIdx.x * 8 + wid;
    int base = (r >= NB) ? NB : 0;       // batch row base

    int ij = idx[(size_t)r * KNN + lane];
    sidx[wid][lane] = ij;

    float cx = pts[(size_t)r * 3 + 0];
    float cy = pts[(size_t)r * 3 + 1];
    float cz = pts[(size_t)r * 3 + 2];

    size_t gr = (size_t)(base + ij) * 3;
    float px = pts[gr + 0], py = pts[gr + 1], pz = pts[gr + 2];

    float rx = cx - px, ry = cy - py, rz = cz - pz;
    float dist = sqrtf(fmaf(rx, rx, fmaf(ry, ry, rz * rz)));
    sgx[wid][lane] = rx;
    sgy[wid][lane] = ry;
    sgz[wid][lane] = rz;
    sgd[wid][lane] = dist;

    // per-lane weight rows, packed {w,w}
    float4 w2r = ((const float4*)w2)[lane];
    u64 w2xx = pk2(w2r.x, w2r.x), w2yy = pk2(w2r.y, w2r.y);
    u64 w2zz = pk2(w2r.z, w2r.z), w2ww = pk2(w2r.w, w2r.w);
    u64 bias2 = pk2(b2[lane], b2[lane]);

    int dlo = lane & 15;
    int h   = lane >> 4;
    float4 w1r = ((const float4*)w1)[dlo];
    u64 w1xx = pk2(w1r.x, w1r.x), w1yy = pk2(w1r.y, w1r.y);
    u64 w1zz = pk2(w1r.z, w1r.z), w1ww = pk2(w1r.w, w1r.w);
    u64 bias1 = pk2(b1[dlo], b1[dlo]);

    __syncwarp();

    u64 ag2 = 0, ag1 = 0;
    float af1 = 0.f;

#pragma unroll
    for (int it = 0; it < 8; it++) {
        int j0 = it * 4;
        // LDS.128 broadcast: two packed neighbor-pairs per component
        ulonglong2 gx = *(const ulonglong2*)&sgx[wid][j0];
        ulonglong2 gy = *(const ulonglong2*)&sgy[wid][j0];
        ulonglong2 gz = *(const ulonglong2*)&sgz[wid][j0];
        ulonglong2 gd = *(const ulonglong2*)&sgd[wid][j0];

        // ---- g2: all 32 lanes (d = lane), both pairs ----
        u64 s0 = fma2(gx.x, w2xx, bias2);
        s0 = fma2(gy.x, w2yy, s0);
        s0 = fma2(gz.x, w2zz, s0);
        s0 = fma2(gd.x, w2ww, s0);
        ag2 = lrelu_acc2(s0, ag2);

        u64 s1 = fma2(gx.y, w2xx, bias2);
        s1 = fma2(gy.y, w2yy, s1);
        s1 = fma2(gz.y, w2zz, s1);
        s1 = fma2(gd.y, w2ww, s1);
        ag2 = lrelu_acc2(s1, ag2);

        // ---- g1: lanes<16 take pair0, lanes>=16 take pair1 (dims dlo) ----
        u64 qx = h ? gx.y : gx.x;
        u64 qy = h ? gy.y : gy.x;
        u64 qz = h ? gz.y : gz.x;
        u64 qd = h ? gd.y : gd.x;
        u64 t = fma2(qx, w1xx, bias1);
        t = fma2(qy, w1yy, t);
        t = fma2(qz, w1zz, t);
        t = fma2(qd, w1ww, t);
        ag1 = lrelu_acc2(t, ag1);

        // ---- f1 gather: lanes<16 rows j0,j0+1; lanes>=16 rows j0+2,j0+3 ----
        int jb = j0 + 2 * h;
        int n0 = sidx[wid][jb];
        int n1 = sidx[wid][jb + 1];
        af1 += g_x1[(size_t)(base + n0) * 16 + dlo];
        af1 += g_x1[(size_t)(base + n1) * 16 + dlo];
    }

    const float inv = 1.0f / 32.0f;

    float2 a2 = up2(ag2);
    g_x3[(size_t)r * 64 + lane] = (a2.x + a2.y) * inv;

    // fold lane-halves for g1 / f1
    u64 ag1o = __shfl_down_sync(0xffffffffu, ag1, 16);
    float af1o = __shfl_down_sync(0xffffffffu, af1, 16);
    if (lane < 16) {
        float2 a1  = up2(ag1);
        float2 a1o = up2(ag1o);
        g_x2[(size_t)r * 32 + lane]      = (a1.x + a1.y + a1o.x + a1o.y) * inv;
        g_x2[(size_t)r * 32 + 16 + lane] = (af1 + af1o) * inv;
    }
}

// ---------------------------------------------------------------------------
// K3a: f2[d] = mean_k x2[nbr_k][d]  (32 dims)  -> g_x3[r][32:64]
// At the LTS chip throughput cap (~11 TB/s of L2 gather) — do not touch.
// ---------------------------------------------------------------------------
__global__ __launch_bounds__(256) void k_gather2(const int* __restrict__ idx)
{
    __shared__ int sidx[8][32];
    int lane = threadIdx.x & 31;
    int wid  = threadIdx.x >> 5;
    int r    = blockIdx.x * 8 + wid;
    int base = (r >= NB) ? NB : 0;

    sidx[wid][lane] = idx[(size_t)r * KNN + lane];
    __syncwarp();

    float acc = 0.f;
#pragma unroll
    for (int j = 0; j < 32; j++) {
        int nr = sidx[wid][j];
        acc += g_x2[(size_t)(base + nr) * 32 + lane];  // coalesced 128B
    }
    g_x3[(size_t)r * 64 + 32 + lane] = acc * (1.0f / 32.0f);
}

// ---------------------------------------------------------------------------
// K3b: out = lrelu(x3 @ wf^T + bf) + g_res
// Single-phase: R6 skeleton (128 thr, 8 pts x 4 outs, x staged in SMEM,
// w via L1-resident LDG.128 from g_wq0, packed FFMA2).
// ---------------------------------------------------------------------------
__global__ __launch_bounds__(128) void k_final(
    const float* __restrict__ bf, float* __restrict__ out)
{
    __shared__ float4 sx4[128 * 17];            // 128 pts x 64 f, padded

    int tid   = threadIdx.x;
    int dhalf = blockIdx.y;                     // 0: outs 0-31, 1: outs 32-63
    int r0    = blockIdx.x * 128;
    int c     = tid & 7;                        // out group: local d = c*4..c*4+3
    int rw    = tid >> 3;                       // 0..15; points p = rw + 16*i
    int dloc  = c * 4;

    u64 acc[8][4];

    {
        const float4* src = (const float4*)g_x3 + (size_t)r0 * 16;
#pragma unroll
        for (int e = tid; e < 2048; e += 128) {
            int p = e >> 4, k4 = e & 15;
            sx4[p * 17 + k4] = src[e];
        }
    }
    __syncthreads();

#pragma unroll
    for (int i = 0; i < 8; i++)
#pragma unroll
        for (int j = 0; j < 4; j++) acc[i][j] = 0ull;

#pragma unroll
    for (int k4 = 0; k4 < 16; k4++) {
        const ulonglong2* wpA = (const ulonglong2*)&g_wq0[dhalf][2 * k4][dloc];
        const ulonglong2* wpB = (const ulonglong2*)&g_wq0[dhalf][2 * k4 + 1][dloc];
        ulonglong2 wv0 = wpA[0], wv1 = wpA[1];
        ulonglong2 wv2 = wpB[0], wv3 = wpB[1];
#pragma unroll
        for (int i = 0; i < 8; i++) {
            ulonglong2 xv = *(const ulonglong2*)&sx4[(rw + 16 * i) * 17 + k4];
            acc[i][0] = fma2(xv.x, wv0.x, acc[i][0]);
            acc[i][0] = fma2(xv.y, wv2.x, acc[i][0]);
            acc[i][1] = fma2(xv.x, wv0.y, acc[i][1]);
            acc[i][1] = fma2(xv.y, wv2.y, acc[i][1]);
            acc[i][2] = fma2(xv.x, wv1.x, acc[i][2]);
            acc[i][2] = fma2(xv.y, wv3.x, acc[i][2]);
            acc[i][3] = fma2(xv.x, wv1.y, acc[i][3]);
            acc[i][3] = fma2(xv.y, wv3.y, acc[i][3]);
        }
    }

    // combine with precomputed residual + store
    float4 bv = *(const float4*)(bf + dhalf * 32 + dloc);
    const float4* res4 = (const float4*)g_res;
    float4* out4 = (float4*)out;
#pragma unroll
    for (int i = 0; i < 8; i++) {
        int p = rw + 16 * i;
        size_t oidx = (size_t)(r0 + p) * 16 + dhalf * 8 + c;
        float4 rv = res4[oidx];
        float4 v;
#pragma unroll
        for (int j = 0; j < 4; j++) {
            float2 s = up2(acc[i][j]);
            (&v.x)[j] = lrelu(s.x + s.y + (&bv.x)[j]) + (&rv.x)[j];
        }
        out4[oidx] = v;
    }
}

// ---------------------------------------------------------------------------
extern "C" void kernel_launch(void* const* d_in, const int* in_sizes, int n_in,
                              void* d_out, int out_size)
{
    const float* points  = (const float*)d_in[0];
    const float* feats   = (const float*)d_in[1];
    const int*   idx     = (const int*)d_in[2];
    const float* w_init  = (const float*)d_in[3];
    const float* b_init  = (const float*)d_in[4];
    const float* w_lfa1  = (const float*)d_in[5];
    const float* b_lfa1  = (const float*)d_in[6];
    const float* w_lfa2  = (const float*)d_in[7];
    const float* b_lfa2  = (const float*)d_in[8];
    const float* w_final = (const float*)d_in[9];
    const float* b_final = (const float*)d_in[10];
    const float* w_res   = (const float*)d_in[11];
    const float* b_res   = (const float*)d_in[12];
    float* out = (float*)d_out;

    k_init_res<<<NPTS / 64, 256>>>(feats, w_init, b_init, w_res, b_res, w_final);
    k_lfa_geo<<<NPTS / 8, 256>>>(points, idx, w_lfa1, b_lfa1, w_lfa2, b_lfa2);
    k_gather2<<<NPTS / 8, 256>>>(idx);
    k_final<<<dim3(NPTS / 128, 2), 128>>>(b_final, out);
}

// round 9
// speedup vs baseline: 1.0898x; 1.0898x over previous
#include <cuda_runtime.h>
#include <cstdint>
#include <math.h>

#define NPTS 131072   // B*N
#define NB   65536    // N (points per batch)
#define KNN  32
#define FD   64

typedef unsigned long long u64;

// Scratch (no allocations allowed)
__device__ float g_x1[NPTS * 16];   // 8 MB   lrelu(feat @ Wi^T)
__device__ float g_x2[NPTS * 32];   // 16 MB  [g1 | f1]
__device__ float g_x3[NPTS * 64];   // 32 MB  [g2 | f2]

// Pre-packed k-pair weights for k_final:
// g_wq[which][dhalf][k2][dloc] = {w[D][2*k2], w[D][2*k2+1]},  D = dhalf*32+dloc
__device__ __align__(16) u64 g_wq[2][2][32][32];

__device__ __forceinline__ float lrelu(float x) { return fmaxf(x, 0.2f * x); }

// ---- packed f32x2 helpers (sm_103a FFMA2 path) ----
__device__ __forceinline__ u64 fma2(u64 a, u64 b, u64 c) {
    u64 r;
    asm("fma.rn.f32x2 %0, %1, %2, %3;" : "=l"(r) : "l"(a), "l"(b), "l"(c));
    return r;
}
__device__ __forceinline__ u64 pk2(float x, float y) {
    u64 r;
    asm("mov.b64 %0, {%1, %2};" : "=l"(r) : "f"(x), "f"(y));
    return r;
}
__device__ __forceinline__ float2 up2(u64 a) {
    float2 v;
    asm("mov.b64 {%0, %1}, %2;" : "=f"(v.x), "=f"(v.y) : "l"(a));
    return v;
}
#define C06_2 0x3F19999A3F19999AULL   // {0.6f, 0.6f}
#define C04_2 0x3ECCCCCD3ECCCCCDULL   // {0.4f, 0.4f}
#define ABSM  0x7FFFFFFF7FFFFFFFULL

// packed lrelu accumulate: acc += lrelu2(s)  where lrelu(x)=0.6x+0.4|x|
__device__ __forceinline__ u64 lrelu_acc2(u64 s, u64 acc) {
    acc = fma2(s, C06_2, acc);
    acc = fma2(s & ABSM, C04_2, acc);
    return acc;
}

__device__ __forceinline__ uint32_t smem_u32(const void* p) {
    uint32_t a;
    asm("{ .reg .u64 t; cvta.to.shared.u64 t, %1; cvt.u32.u64 %0, t; }"
        : "=r"(a) : "l"(p));
    return a;
}
__device__ __forceinline__ void cp16(uint32_t dst, const void* src) {
    asm volatile("cp.async.cg.shared.global [%0], [%1], 16;"
                 :: "r"(dst), "l"(src) : "memory");
}

// ---------------------------------------------------------------------------
// K0: pack w_final / w_res rows into k-pair u64 chunks (one tiny block).
// ---------------------------------------------------------------------------
__global__ __launch_bounds__(256) void k_packw(
    const float* __restrict__ wf, const float* __restrict__ wr)
{
    int t = threadIdx.x;
    u64* dst = &g_wq[0][0][0][0];
#pragma unroll
    for (int e = t; e < 4096; e += 256) {
        int which = e >> 11;
        int rem   = e & 2047;
        int dh    = rem >> 10;
        int k2    = (rem >> 5) & 31;
        int dloc  = rem & 31;
        const float* src = which ? wr : wf;
        dst[e] = *(const u64*)(src + (size_t)(dh * 32 + dloc) * 64 + k2 * 2);
    }
}

// ---------------------------------------------------------------------------
// K1: x1 = lrelu(features @ w_init^T + b_init)   (NPTS, 16)
// ---------------------------------------------------------------------------
__global__ __launch_bounds__(256) void k_init(
    const float* __restrict__ feat, const float* __restrict__ w,
    const float* __restrict__ b)
{
    __shared__ float4 sf4[256];          // 16 points x 64 feats
    __shared__ float  swt[64 * 16];      // transposed w_init
    __shared__ float  sb[16];
    const float* sf = (const float*)sf4;

    int tid = threadIdx.x;
    int fb  = blockIdx.x * 16;

    const float4* f4 = (const float4*)feat + (size_t)fb * 16;
    sf4[tid] = f4[tid];

#pragma unroll
    for (int e = tid; e < 1024; e += 256) {
        int d = e >> 6, i = e & 63;
        swt[i * 16 + d] = w[e];
    }
    if (tid < 16) sb[tid] = b[tid];
    __syncthreads();

    int p = tid >> 4, d = tid & 15;
    float acc = sb[d];
#pragma unroll
    for (int i = 0; i < 64; i++)
        acc = fmaf(sf[p * 64 + i], swt[i * 16 + d], acc);

    g_x1[(size_t)fb * 16 + tid] = lrelu(acc);
}

// ---------------------------------------------------------------------------
// K2: fused geo-MLPs of lfa1 + lfa2 (shared geometry) + x1 gather-mean.
// One warp per point. Geo staged SoA in SMEM; packed f32x2 over neighbor pairs.
// ---------------------------------------------------------------------------
__global__ __launch_bounds__(256) void k_lfa_geo(
    const float* __restrict__ pts, const int* __restrict__ idx,
    const float* __restrict__ w1, const float* __restrict__ b1,
    const float* __restrict__ w2, const float* __restrict__ b2)
{
    __shared__ __align__(16) float sgx[8][32];
    __shared__ __align__(16) float sgy[8][32];
    __shared__ __align__(16) float sgz[8][32];
    __shared__ __align__(16) float sgd[8][32];
    __shared__ int sidx[8][32];

    int lane = threadIdx.x & 31;
    int wid  = threadIdx.x >> 5;
    int r    = blockIdx.x * 8 + wid;
    int base = (r >= NB) ? NB : 0;       // batch row base

    int ij = idx[(size_t)r * KNN + lane];
    sidx[wid][lane] = ij;

    float cx = pts[(size_t)r * 3 + 0];
    float cy = pts[(size_t)r * 3 + 1];
    float cz = pts[(size_t)r * 3 + 2];

    size_t gr = (size_t)(base + ij) * 3;
    float px = pts[gr + 0], py = pts[gr + 1], pz = pts[gr + 2];

    float rx = cx - px, ry = cy - py, rz = cz - pz;
    float dist = sqrtf(fmaf(rx, rx, fmaf(ry, ry, rz * rz)));
    sgx[wid][lane] = rx;
    sgy[wid][lane] = ry;
    sgz[wid][lane] = rz;
    sgd[wid][lane] = dist;

    // per-lane weight rows, packed {w,w}
    float4 w2r = ((const float4*)w2)[lane];
    u64 w2xx = pk2(w2r.x, w2r.x), w2yy = pk2(w2r.y, w2r.y);
    u64 w2zz = pk2(w2r.z, w2r.z), w2ww = pk2(w2r.w, w2r.w);
    u64 bias2 = pk2(b2[lane], b2[lane]);

    int dlo = lane & 15;
    int h   = lane >> 4;
    float4 w1r = ((const float4*)w1)[dlo];
    u64 w1xx = pk2(w1r.x, w1r.x), w1yy = pk2(w1r.y, w1r.y);
    u64 w1zz = pk2(w1r.z, w1r.z), w1ww = pk2(w1r.w, w1r.w);
    u64 bias1 = pk2(b1[dlo], b1[dlo]);

    __syncwarp();

    u64 ag2 = 0, ag1 = 0;
    float af1 = 0.f;

#pragma unroll
    for (int it = 0; it < 8; it++) {
        int j0 = it * 4;
        // LDS.128 broadcast: two packed neighbor-pairs per component
        ulonglong2 gx = *(const ulonglong2*)&sgx[wid][j0];
        ulonglong2 gy = *(const ulonglong2*)&sgy[wid][j0];
        ulonglong2 gz = *(const ulonglong2*)&sgz[wid][j0];
        ulonglong2 gd = *(const ulonglong2*)&sgd[wid][j0];

        // ---- g2: all 32 lanes (d = lane), both pairs ----
        u64 s0 = fma2(gx.x, w2xx, bias2);
        s0 = fma2(gy.x, w2yy, s0);
        s0 = fma2(gz.x, w2zz, s0);
        s0 = fma2(gd.x, w2ww, s0);
        ag2 = lrelu_acc2(s0, ag2);

        u64 s1 = fma2(gx.y, w2xx, bias2);
        s1 = fma2(gy.y, w2yy, s1);
        s1 = fma2(gz.y, w2zz, s1);
        s1 = fma2(gd.y, w2ww, s1);
        ag2 = lrelu_acc2(s1, ag2);

        // ---- g1: lanes<16 take pair0, lanes>=16 take pair1 (dims dlo) ----
        u64 qx = h ? gx.y : gx.x;
        u64 qy = h ? gy.y : gy.x;
        u64 qz = h ? gz.y : gz.x;
        u64 qd = h ? gd.y : gd.x;
        u64 t = fma2(qx, w1xx, bias1);
        t = fma2(qy, w1yy, t);
        t = fma2(qz, w1zz, t);
        t = fma2(qd, w1ww, t);
        ag1 = lrelu_acc2(t, ag1);

        // ---- f1 gather: lanes<16 rows j0,j0+1; lanes>=16 rows j0+2,j0+3 ----
        int jb = j0 + 2 * h;
        int n0 = sidx[wid][jb];
        int n1 = sidx[wid][jb + 1];
        af1 += g_x1[(size_t)(base + n0) * 16 + dlo];
        af1 += g_x1[(size_t)(base + n1) * 16 + dlo];
    }

    const float inv = 1.0f / 32.0f;

    float2 a2 = up2(ag2);
    g_x3[(size_t)r * 64 + lane] = (a2.x + a2.y) * inv;

    // fold lane-halves for g1 / f1
    u64 ag1o = __shfl_down_sync(0xffffffffu, ag1, 16);
    float af1o = __shfl_down_sync(0xffffffffu, af1, 16);
    if (lane < 16) {
        float2 a1  = up2(ag1);
        float2 a1o = up2(ag1o);
        g_x2[(size_t)r * 32 + lane]      = (a1.x + a1.y + a1o.x + a1o.y) * inv;
        g_x2[(size_t)r * 32 + 16 + lane] = (af1 + af1o) * inv;
    }
}

// ---------------------------------------------------------------------------
// K3a: f2[d] = mean_k x2[nbr_k][d]  (32 dims)  -> g_x3[r][32:64]
// At the LTS chip throughput cap (~11 TB/s of L2 gather) — do not touch.
// ---------------------------------------------------------------------------
__global__ __launch_bounds__(256) void k_gather2(const int* __restrict__ idx)
{
    __shared__ int sidx[8][32];
    int lane = threadIdx.x & 31;
    int wid  = threadIdx.x >> 5;
    int r    = blockIdx.x * 8 + wid;
    int base = (r >= NB) ? NB : 0;

    sidx[wid][lane] = idx[(size_t)r * KNN + lane];
    __syncwarp();

    float acc = 0.f;
#pragma unroll
    for (int j = 0; j < 32; j++) {
        int nr = sidx[wid][j];
        acc += g_x2[(size_t)(base + nr) * 32 + lane];  // coalesced 128B
    }
    g_x3[(size_t)r * 64 + 32 + lane] = acc * (1.0f / 32.0f);
}

// ---------------------------------------------------------------------------
// K3b: out = lrelu(x3 @ wf^T + bf) + lrelu(feat @ wr^T + br)
// Two-phase, cp.async double-buffered: both tiles stream in up front; phase-B
// fill overlaps phase-A compute. w via L1-resident LDG.128 from g_wq,
// packed FFMA2, zero packing movs. 128 thr, 8 pts x 4 outs.
// ---------------------------------------------------------------------------
__global__ __launch_bounds__(128) void k_final(
    const float* __restrict__ feat,
    const float* __restrict__ bf, const float* __restrict__ br,
    float* __restrict__ out)
{
    __shared__ float4 sxA[128 * 17];            // x3 tile, padded
    __shared__ float4 sxB[128 * 17];            // feat tile, padded

    int tid   = threadIdx.x;
    int dhalf = blockIdx.y;                     // 0: outs 0-31, 1: outs 32-63
    int r0    = blockIdx.x * 128;
    int c     = tid & 7;                        // out group: local d = c*4..c*4+3
    int rw    = tid >> 3;                       // 0..15; points p = rw + 16*i
    int dloc  = c * 4;

    // ---- stream both tiles in via cp.async (B overlaps A's compute) ----
    {
        uint32_t sA = smem_u32(sxA);
        uint32_t sB = smem_u32(sxB);
        const float4* srcA = (const float4*)g_x3 + (size_t)r0 * 16;
        const float4* srcB = (const float4*)feat + (size_t)r0 * 16;
#pragma unroll
        for (int e = tid; e < 2048; e += 128) {
            int p = e >> 4, k4 = e & 15;
            cp16(sA + (uint32_t)(p * 17 + k4) * 16, srcA + e);
        }
        asm volatile("cp.async.commit_group;" ::: "memory");
#pragma unroll
        for (int e = tid; e < 2048; e += 128) {
            int p = e >> 4, k4 = e & 15;
            cp16(sB + (uint32_t)(p * 17 + k4) * 16, srcB + e);
        }
        asm volatile("cp.async.commit_group;" ::: "memory");
    }

    u64 acc[8][4];
    float po[8][4];

    // ================ phase A: x3 @ wf^T ================
    asm volatile("cp.async.wait_group 1;" ::: "memory");
    __syncthreads();

#pragma unroll
    for (int i = 0; i < 8; i++)
#pragma unroll
        for (int j = 0; j < 4; j++) acc[i][j] = 0ull;

#pragma unroll
    for (int k4 = 0; k4 < 16; k4++) {
        const ulonglong2* wpA = (const ulonglong2*)&g_wq[0][dhalf][2 * k4][dloc];
        const ulonglong2* wpB = (const ulonglong2*)&g_wq[0][dhalf][2 * k4 + 1][dloc];
        ulonglong2 wv0 = wpA[0], wv1 = wpA[1];
        ulonglong2 wv2 = wpB[0], wv3 = wpB[1];
#pragma unroll
        for (int i = 0; i < 8; i++) {
            ulonglong2 xv = *(const ulonglong2*)&sxA[(rw + 16 * i) * 17 + k4];
            acc[i][0] = fma2(xv.x, wv0.x, acc[i][0]);
            acc[i][0] = fma2(xv.y, wv2.x, acc[i][0]);
            acc[i][1] = fma2(xv.x, wv0.y, acc[i][1]);
            acc[i][1] = fma2(xv.y, wv2.y, acc[i][1]);
            acc[i][2] = fma2(xv.x, wv1.x, acc[i][2]);
            acc[i][2] = fma2(xv.y, wv3.x, acc[i][2]);
            acc[i][3] = fma2(xv.x, wv1.y, acc[i][3]);
            acc[i][3] = fma2(xv.y, wv3.y, acc[i][3]);
        }
    }

    {
        float4 bv = *(const float4*)(bf + dhalf * 32 + dloc);
#pragma unroll
        for (int i = 0; i < 8; i++)
#pragma unroll
            for (int j = 0; j < 4; j++) {
                float2 v = up2(acc[i][j]);
                po[i][j] = lrelu(v.x + v.y + (&bv.x)[j]);
            }
    }

    // ================ phase B: feat @ wr^T ================
    asm volatile("cp.async.wait_group 0;" ::: "memory");
    __syncthreads();

#pragma unroll
    for (int i = 0; i < 8; i++)
#pragma unroll
        for (int j = 0; j < 4; j++) acc[i][j] = 0ull;

#pragma unroll
    for (int k4 = 0; k4 < 16; k4++) {
        const ulonglong2* wpA = (const ulonglong2*)&g_wq[1][dhalf][2 * k4][dloc];
        const ulonglong2* wpB = (const ulonglong2*)&g_wq[1][dhalf][2 * k4 + 1][dloc];
        ulonglong2 wv0 = wpA[0], wv1 = wpA[1];
        ulonglong2 wv2 = wpB[0], wv3 = wpB[1];
#pragma unroll
        for (int i = 0; i < 8; i++) {
            ulonglong2 xv = *(const ulonglong2*)&sxB[(rw + 16 * i) * 17 + k4];
            acc[i][0] = fma2(xv.x, wv0.x, acc[i][0]);
            acc[i][0] = fma2(xv.y, wv2.x, acc[i][0]);
            acc[i][1] = fma2(xv.x, wv0.y, acc[i][1]);
            acc[i][1] = fma2(xv.y, wv2.y, acc[i][1]);
            acc[i][2] = fma2(xv.x, wv1.x, acc[i][2]);
            acc[i][2] = fma2(xv.y, wv3.x, acc[i][2]);
            acc[i][3] = fma2(xv.x, wv1.y, acc[i][3]);
            acc[i][3] = fma2(xv.y, wv3.y, acc[i][3]);
        }
    }

    // combine + store (float4 per point)
    float4 bv2 = *(const float4*)(br + dhalf * 32 + dloc);
    float4* out4 = (float4*)out;
#pragma unroll
    for (int i = 0; i < 8; i++) {
        int p = rw + 16 * i;
        float4 v;
#pragma unroll
        for (int j = 0; j < 4; j++) {
            float2 w2 = up2(acc[i][j]);
            (&v.x)[j] = po[i][j] + lrelu(w2.x + w2.y + (&bv2.x)[j]);
        }
        out4[(size_t)(r0 + p) * 16 + dhalf * 8 + c] = v;
    }
}

// ---------------------------------------------------------------------------
extern "C" void kernel_launch(void* const* d_in, const int* in_sizes, int n_in,
                              void* d_out, int out_size)
{
    const float* points  = (const float*)d_in[0];
    const float* feats   = (const float*)d_in[1];
    const int*   idx     = (const int*)d_in[2];
    const float* w_init  = (const float*)d_in[3];
    const float* b_init  = (const float*)d_in[4];
    const float* w_lfa1  = (const float*)d_in[5];
    const float* b_lfa1  = (const float*)d_in[6];
    const float* w_lfa2  = (const float*)d_in[7];
    const float* b_lfa2  = (const float*)d_in[8];
    const float* w_final = (const float*)d_in[9];
    const float* b_final = (const float*)d_in[10];
    const float* w_res   = (const float*)d_in[11];
    const float* b_res   = (const float*)d_in[12];
    float* out = (float*)d_out;

    k_packw<<<1, 256>>>(w_final, w_res);
    k_init<<<NPTS / 16, 256>>>(feats, w_init, b_init);
    k_lfa_geo<<<NPTS / 8, 256>>>(points, idx, w_lfa1, b_lfa1, w_lfa2, b_lfa2);
    k_gather2<<<NPTS / 8, 256>>>(idx);
    k_final<<<dim3(NPTS / 128, 2), 128>>>(feats, b_final, b_res, out);
}